// round 15
// baseline (speedup 1.0000x reference)
#include <cuda_runtime.h>
#include <cuda_fp16.h>
#include <cstdint>
#include <math.h>

// Problem dims (fixed by the reference)
#define HID   2560
#define SEQ   2048
#define BATCH 4
#define IND   2048
#define OUTD  2048
#define MROWS (BATCH * SEQ)   // 8192

#define NCHUNK 16
#define CLEN   (SEQ / NCHUNK) // 128

// ---------------------------------------------------------------------------
// Scratch (device globals -- no cudaMalloc allowed)
// ---------------------------------------------------------------------------
__device__ __half g_wlh  [(size_t)IND * HID];     // fp16 Wl^T [HID][IND]
__device__ __half g_wrh  [(size_t)IND * HID];     // fp16 Wr^T
__device__ __half g_wah  [(size_t)HID * HID];     // fp16 Wa^T
__device__ __half g_wih  [(size_t)HID * HID];     // fp16 Wi^T
__device__ __half g_woh  [(size_t)HID * OUTD];    // fp16 Wo^T [OUTD][HID]
__device__ __half g_lefth[(size_t)MROWS * HID];   // fp16 gelu output
__device__ __half g_rinh [(size_t)MROWS * HID];   // fp16 x@Wr+br
__device__ __half g_convh[(size_t)MROWS * HID];   // fp16 conv output
__device__ __half g_rh   [(size_t)MROWS * HID];   // fp16 r = sigmoid(conv@Wa+ba)
__device__ __half g_dh   [(size_t)MROWS * HID];   // fp16 drive
__device__ __half g_yh   [(size_t)MROWS * HID];   // fp16 left*h
__device__ float  g_ra   [(size_t)MROWS * HID];   // a (fp32)
__device__ float  g_cp   [BATCH * NCHUNK * HID];
__device__ float  g_ch   [BATCH * NCHUNK * HID];
__device__ float  g_lamc [HID];                   // -8*softplus(-lam)

// ---------------------------------------------------------------------------
// helpers
// ---------------------------------------------------------------------------
__device__ __forceinline__ uint32_t smem_u32(const void* p) {
    uint32_t a;
    asm("{ .reg .u64 t; cvta.to.shared.u64 t, %1; cvt.u32.u64 %0, t; }" : "=r"(a) : "l"(p));
    return a;
}
__device__ __forceinline__ void cp16(uint32_t dst, const void* src) {
    asm volatile("cp.async.cg.shared.global [%0], [%1], 16;" :: "r"(dst), "l"(src));
}
#define CP_COMMIT() asm volatile("cp.async.commit_group;" ::: "memory")
#define CP_WAIT1()  asm volatile("cp.async.wait_group 1;" ::: "memory")

__device__ __forceinline__ void ldsm_x4(uint32_t* r, uint32_t addr) {
    asm volatile("ldmatrix.sync.aligned.m8n8.x4.shared.b16 {%0,%1,%2,%3}, [%4];"
                 : "=r"(r[0]), "=r"(r[1]), "=r"(r[2]), "=r"(r[3]) : "r"(addr));
}
__device__ __forceinline__ void mma16(float* d, const uint32_t* a, const uint32_t* b) {
    asm volatile(
        "mma.sync.aligned.m16n8k16.row.col.f32.f16.f16.f32 "
        "{%0,%1,%2,%3},{%4,%5,%6,%7},{%8,%9},{%0,%1,%2,%3};\n"
        : "+f"(d[0]), "+f"(d[1]), "+f"(d[2]), "+f"(d[3])
        : "r"(a[0]), "r"(a[1]), "r"(a[2]), "r"(a[3]),
          "r"(b[0]), "r"(b[1]));
}

__device__ __forceinline__ float sqrt_ap(float x) {
    float y;
    asm("sqrt.approx.f32 %0, %1;" : "=f"(y) : "f"(x));
    return y;
}
__device__ __forceinline__ float tanh_ap(float x) {
    float y;
    asm("tanh.approx.f32 %0, %1;" : "=f"(y) : "f"(x));
    return y;
}
__device__ __forceinline__ float sigmoid_f(float v) {
    return fmaf(0.5f, tanh_ap(0.5f * v), 0.5f);
}
__device__ __forceinline__ float gelu_f(float v) {
    float c = 0.7978845608028654f * (v + 0.044715f * v * v * v);
    return 0.5f * v * (1.0f + tanh_ap(c));
}

// ---------------------------------------------------------------------------
// fp16 tensor-core GEMM: C = act(A[M,K] @ Bt[N,K]^T + bias), fp32 accumulate.
// B fp16 pre-transposed [N][K]. CTA 128x128, 256 threads, 8 warps (2x4),
// warp tile 64x32, mma m16n8k16, k-chunk 64, 3-stage pipeline, 2 CTAs/SM.
// CVTA=0: A fp16, staged via cp.async.
// CVTA=1: A fp32 (A32), staged via LDG+cvt+STS (A visibility via barrier;
//         wait_group guards B only). Crossbar bytes unchanged.
// ACT: 0 none->C(f32), 2 sigmoid->Ch(f16),
//      3 sigmoid + fused RG-LRU gate (Rbuf/Ubuf f16 in; a->Aout f32,
//        drive->Ch f16),
//      4 dual: grid.x first half gelu->Ch(f16), second half none->Ch2(f16)
//        using B2/bias2.
// smem: A stages [3][128][128B] @0, B stages same @49152. Total 96KB.
// ---------------------------------------------------------------------------
#define SMB_OFF 49152
#define SM_BYTES 98304

template <int ACT, int CVTA>
__global__ void __launch_bounds__(256, 2)
gemm_h(const __half* __restrict__ A, const float* __restrict__ A32,
       const __half* __restrict__ B,
       const float* __restrict__ bias, float* __restrict__ C,
       __half* __restrict__ Ch,
       int M, int N, int K,
       const __half* __restrict__ Rbuf, const __half* __restrict__ Ubuf,
       const float* __restrict__ lamc, float* __restrict__ Aout,
       const __half* B2, const float* bias2, __half* Ch2)
{
    extern __shared__ char sm[];
    const int tid  = threadIdx.x;
    const int lane = tid & 31;
    const int warp = tid >> 5;
    const int wm   = (warp >> 2) * 64;
    const int wn   = (warp & 3) * 32;
    const int bM   = blockIdx.y * 128;
    const uint32_t smb = smem_u32(sm);
    const int NK = K >> 6;            // k-chunk 64

    int bN;
    int act = ACT;
    if (ACT == 4) {
        int half_ = gridDim.x >> 1;
        if (blockIdx.x >= half_) {
            B = B2; bias = bias2; Ch = Ch2; act = 0;
            bN = (blockIdx.x - half_) * 128;
        } else {
            act = 1;
            bN = blockIdx.x * 128;
        }
    } else {
        bN = blockIdx.x * 128;
    }

    float acc[4][4][4];
#pragma unroll
    for (int i = 0; i < 4; i++)
#pragma unroll
        for (int j = 0; j < 4; j++)
#pragma unroll
            for (int k = 0; k < 4; k++) acc[i][j][k] = 0.0f;

    auto load_stage = [&](int kc, int s) {
        const int k0 = kc << 6;
        // A: 128 m-rows x 64 halfs (128B rows, SW128)
#pragma unroll
        for (int i = 0; i < 4; i++) {
            int idx = tid + (i << 8);
            int r = idx >> 3, c = idx & 7;
            uint32_t o = (uint32_t)(r * 128 + c * 16);
            o ^= (uint32_t)((r & 7) << 4);
            if (CVTA) {
                const float* src = A32 + (size_t)(bM + r) * K + k0 + (c << 3);
                float4 v0 = *(const float4*)src;
                float4 v1 = *(const float4*)(src + 4);
                uint4 w;
                ((__half2*)&w)[0] = __floats2half2_rn(v0.x, v0.y);
                ((__half2*)&w)[1] = __floats2half2_rn(v0.z, v0.w);
                ((__half2*)&w)[2] = __floats2half2_rn(v1.x, v1.y);
                ((__half2*)&w)[3] = __floats2half2_rn(v1.z, v1.w);
                *(uint4*)(sm + s * 16384 + o) = w;
            } else {
                cp16(smb + (uint32_t)s * 16384u + o,
                     A + (size_t)(bM + r) * K + k0 + (c << 3));
            }
        }
        // B (pre-transposed [N][K]): 128 n-rows x 64 halfs
#pragma unroll
        for (int i = 0; i < 4; i++) {
            int idx = tid + (i << 8);
            int r = idx >> 3, c = idx & 7;
            uint32_t o = (uint32_t)(r * 128 + c * 16);
            o ^= (uint32_t)((r & 7) << 4);
            cp16(smb + SMB_OFF + (uint32_t)s * 16384u + o,
                 B + (size_t)(bN + r) * K + k0 + (c << 3));
        }
    };

    load_stage(0, 0); CP_COMMIT();
    load_stage(1, 1); CP_COMMIT();
    if (CVTA) __syncthreads();   // A of stages 0,1 via STS: make visible

    const int jmat = lane >> 3;       // 0..3
    const int r8   = lane & 7;

    int stage = 0;
    for (int kc = 0; kc < NK; kc++) {
        CP_WAIT1();
        __syncthreads();
        if (kc + 2 < NK) load_stage(kc + 2, (stage + 2) % 3);
        CP_COMMIT();

        const uint32_t aBase = smb + (uint32_t)stage * 16384u;
        const uint32_t bBase = smb + SMB_OFF + (uint32_t)stage * 16384u;

#pragma unroll
        for (int ks = 0; ks < 4; ks++) {   // 4 k-steps of 16 halfs (32B)
            uint32_t af[4][4];
#pragma unroll
            for (int mt = 0; mt < 4; mt++) {
                int row = wm + mt * 16 + ((jmat & 1) << 3) + r8;
                uint32_t o = (uint32_t)(row * 128 + ks * 32 + ((jmat >> 1) << 4));
                o ^= (uint32_t)(r8 << 4);
                ldsm_x4(af[mt], aBase + o);
            }
            uint32_t bf[4][2];
#pragma unroll
            for (int p = 0; p < 2; p++) {
                int nrow = wn + p * 16 + ((jmat >> 1) << 3) + r8;
                uint32_t o = (uint32_t)(nrow * 128 + ks * 32 + ((jmat & 1) << 4));
                o ^= (uint32_t)(r8 << 4);
                uint32_t t[4];
                ldsm_x4(t, bBase + o);
                bf[p * 2 + 0][0] = t[0]; bf[p * 2 + 0][1] = t[1];
                bf[p * 2 + 1][0] = t[2]; bf[p * 2 + 1][1] = t[3];
            }
#pragma unroll
            for (int mt = 0; mt < 4; mt++)
#pragma unroll
                for (int nt = 0; nt < 4; nt++)
                    mma16(acc[mt][nt], af[mt], bf[nt]);
        }
        stage = (stage + 1) % 3;
    }

    // --------------------------- epilogue ---------------------------------
#pragma unroll
    for (int mt = 0; mt < 4; mt++) {
        int row0 = bM + wm + mt * 16 + (lane >> 2);
#pragma unroll
        for (int nt = 0; nt < 4; nt++) {
            int col = bN + wn + nt * 8 + ((lane & 3) << 1);
            float b0 = bias[col], b1 = bias[col + 1];
            if (ACT == 3) {
                float lc0 = lamc[col], lc1 = lamc[col + 1];
#pragma unroll
                for (int rr = 0; rr < 2; rr++) {
                    size_t idx = (size_t)(row0 + rr * 8) * N + col;
                    float i0 = sigmoid_f(acc[mt][nt][rr * 2 + 0] + b0);
                    float i1 = sigmoid_f(acc[mt][nt][rr * 2 + 1] + b1);
                    __half2 rh = *(const __half2*)(Rbuf + idx);
                    __half2 uh = *(const __half2*)(Ubuf + idx);
                    float a0 = __expf(lc0 * __half2float(__low2half(rh)));
                    float a1 = __expf(lc1 * __half2float(__high2half(rh)));
                    float be0 = sqrt_ap(fmaxf(1.0f - a0 * a0, 1e-12f));
                    float be1 = sqrt_ap(fmaxf(1.0f - a1 * a1, 1e-12f));
                    float d0 = be0 * i0 * __half2float(__low2half(uh));
                    float d1 = be1 * i1 * __half2float(__high2half(uh));
                    *(float2*)(Aout + idx) = make_float2(a0, a1);
                    *(__half2*)(Ch + idx) = __floats2half2_rn(d0, d1);
                }
            } else if (ACT == 4) {
#pragma unroll
                for (int rr = 0; rr < 2; rr++) {
                    float v0 = acc[mt][nt][rr * 2 + 0] + b0;
                    float v1 = acc[mt][nt][rr * 2 + 1] + b1;
                    size_t idx = (size_t)(row0 + rr * 8) * N + col;
                    if (act == 1) { v0 = gelu_f(v0); v1 = gelu_f(v1); }
                    *(__half2*)(Ch + idx) = __floats2half2_rn(v0, v1);
                }
            } else if (ACT == 2) {
#pragma unroll
                for (int rr = 0; rr < 2; rr++) {
                    float v0 = sigmoid_f(acc[mt][nt][rr * 2 + 0] + b0);
                    float v1 = sigmoid_f(acc[mt][nt][rr * 2 + 1] + b1);
                    *(__half2*)(Ch + (size_t)(row0 + rr * 8) * N + col) =
                        __floats2half2_rn(v0, v1);
                }
            } else {
#pragma unroll
                for (int rr = 0; rr < 2; rr++) {
                    float v0 = acc[mt][nt][rr * 2 + 0] + b0;
                    float v1 = acc[mt][nt][rr * 2 + 1] + b1;
                    *(float2*)(C + (size_t)(row0 + rr * 8) * N + col) = make_float2(v0, v1);
                }
            }
        }
    }
}

// ---------------------------------------------------------------------------
// One 32x32 transpose+convert tile: dst[N][K] = half(src[K][N])
// ---------------------------------------------------------------------------
__device__ __forceinline__ void tr_tile(const float* __restrict__ src,
                                        __half* __restrict__ dst,
                                        int K, int N, int bx, int by)
{
    __shared__ float t[32][33];
    int k0 = by * 32, n0 = bx * 32;
    int tx = threadIdx.x & 31, ty = threadIdx.x >> 5;
#pragma unroll
    for (int i = 0; i < 32; i += 8)
        t[ty + i][tx] = src[(size_t)(k0 + ty + i) * N + n0 + tx];
    __syncthreads();
#pragma unroll
    for (int i = 0; i < 32; i += 8)
        dst[(size_t)(n0 + ty + i) * K + k0 + tx] = __float2half_rn(t[tx][ty + i]);
}

// ---------------------------------------------------------------------------
// Consolidated prep: 5 weight transposes + lamc, one launch (x handled
// in-GEMM now).
// ---------------------------------------------------------------------------
#define NB_WL 5120   // 80*64
#define NB_WA 6400   // 80*80
#define NB_WO 5120   // 64*80
#define NB_PREP (NB_WL*2 + NB_WA*2 + NB_WO + 10)

__global__ void prep_all(const float* __restrict__ Wl, const float* __restrict__ Wr,
                         const float* __restrict__ Wa, const float* __restrict__ Wi,
                         const float* __restrict__ Wo, const float* __restrict__ lam)
{
    int id = blockIdx.x;
    if (id < NB_WL) {
        tr_tile(Wl, g_wlh, IND, HID, id % 80, id / 80);
    } else if (id < 2 * NB_WL) {
        id -= NB_WL;
        tr_tile(Wr, g_wrh, IND, HID, id % 80, id / 80);
    } else if (id < 2 * NB_WL + NB_WA) {
        id -= 2 * NB_WL;
        tr_tile(Wa, g_wah, HID, HID, id % 80, id / 80);
    } else if (id < 2 * NB_WL + 2 * NB_WA) {
        id -= 2 * NB_WL + NB_WA;
        tr_tile(Wi, g_wih, HID, HID, id % 80, id / 80);
    } else if (id < 2 * NB_WL + 2 * NB_WA + NB_WO) {
        id -= 2 * NB_WL + 2 * NB_WA;
        tr_tile(Wo, g_woh, HID, OUTD, id % 64, id / 64);
    } else {
        id -= 2 * NB_WL + 2 * NB_WA + NB_WO;
        int h = id * 256 + threadIdx.x;
        if (h < HID) g_lamc[h] = -8.0f * log1pf(__expf(-lam[h]));
    }
}

// ---------------------------------------------------------------------------
// Causal depthwise conv1d (width 4, left pad 3); fp16 in/out, 8 elems/thread
// ---------------------------------------------------------------------------
__global__ void conv_kernel(const float* __restrict__ w, const float* __restrict__ cb)
{
    int i = (blockIdx.x * blockDim.x + threadIdx.x) * 8;
    int h = i % HID;
    int s = (i / HID) % SEQ;
    const __half* base = g_rinh + (size_t)i;
    float acc[8];
#pragma unroll
    for (int e = 0; e < 8; e += 4) {
        float4 b4 = *(const float4*)(cb + h + e);
        acc[e] = b4.x; acc[e + 1] = b4.y; acc[e + 2] = b4.z; acc[e + 3] = b4.w;
    }
#pragma unroll
    for (int k = 0; k < 4; k++) {
        int t = s - 3 + k;
        if (t >= 0) {
            uint4 vv = *(const uint4*)(base + (long)(k - 3) * HID);
            const __half2* vh = (const __half2*)&vv;
#pragma unroll
            for (int e = 0; e < 8; e += 4) {
                float4 wv = *(const float4*)(w + k * HID + h + e);
                __half2 p0 = vh[e / 2], p1 = vh[e / 2 + 1];
                acc[e + 0] = fmaf(wv.x, __half2float(__low2half(p0)),  acc[e + 0]);
                acc[e + 1] = fmaf(wv.y, __half2float(__high2half(p0)), acc[e + 1]);
                acc[e + 2] = fmaf(wv.z, __half2float(__low2half(p1)),  acc[e + 2]);
                acc[e + 3] = fmaf(wv.w, __half2float(__high2half(p1)), acc[e + 3]);
            }
        }
    }
    uint4 ov;
    __half2* oh = (__half2*)&ov;
    oh[0] = __floats2half2_rn(acc[0], acc[1]);
    oh[1] = __floats2half2_rn(acc[2], acc[3]);
    oh[2] = __floats2half2_rn(acc[4], acc[5]);
    oh[3] = __floats2half2_rn(acc[6], acc[7]);
    *(uint4*)(g_convh + i) = ov;
}

// ---------------------------------------------------------------------------
// Chunked scan (2 passes), chunk length 128, 16 chunks/sequence.
// 2 h-channels per thread (a: f32, drive: f16). (Proven R12 form.)
// ---------------------------------------------------------------------------
__global__ void scan_pass1()
{
    int idx = (blockIdx.x * blockDim.x + threadIdx.x) * 2;  // over B*NCHUNK*HID
    int h = idx % HID;
    int t = idx / HID;
    int c = t % NCHUNK;
    int b = t / NCHUNK;
    size_t base = ((size_t)b * SEQ + (size_t)c * CLEN) * HID + h;
    float2 P = make_float2(1.0f, 1.0f), hs = make_float2(0.0f, 0.0f);
#pragma unroll 4
    for (int s = 0; s < CLEN; s++) {
        size_t o = base + (size_t)s * HID;
        float2 a = *(const float2*)(g_ra + o);
        __half2 dh = *(const __half2*)(g_dh + o);
        P.x *= a.x; P.y *= a.y;
        hs.x = fmaf(a.x, hs.x, __half2float(__low2half(dh)));
        hs.y = fmaf(a.y, hs.y, __half2float(__high2half(dh)));
    }
    size_t oo = ((size_t)b * NCHUNK + c) * HID + h;
    *(float2*)(g_cp + oo) = P;
    *(float2*)(g_ch + oo) = hs;
}

__global__ void scan_pass3()
{
    int idx = (blockIdx.x * blockDim.x + threadIdx.x) * 2;
    int h = idx % HID;
    int t = idx / HID;
    int c = t % NCHUNK;
    int b = t / NCHUNK;
    // stitch: fold chunk summaries 0..c-1
    float2 hin = make_float2(0.0f, 0.0f);
    for (int cc = 0; cc < c; cc++) {
        size_t oo = ((size_t)b * NCHUNK + cc) * HID + h;
        float2 p = *(const float2*)(g_cp + oo);
        float2 hh = *(const float2*)(g_ch + oo);
        hin.x = fmaf(p.x, hin.x, hh.x);
        hin.y = fmaf(p.y, hin.y, hh.y);
    }
    size_t base = ((size_t)b * SEQ + (size_t)c * CLEN) * HID + h;
    float2 hs = hin;
#pragma unroll 4
    for (int s = 0; s < CLEN; s++) {
        size_t o = base + (size_t)s * HID;
        float2 a = *(const float2*)(g_ra + o);
        __half2 dh = *(const __half2*)(g_dh + o);
        __half2 lh = *(const __half2*)(g_lefth + o);
        hs.x = fmaf(a.x, hs.x, __half2float(__low2half(dh)));
        hs.y = fmaf(a.y, hs.y, __half2float(__high2half(dh)));
        *(__half2*)(g_yh + o) =
            __floats2half2_rn(__half2float(__low2half(lh)) * hs.x,
                              __half2float(__high2half(lh)) * hs.y);
    }
}

// ---------------------------------------------------------------------------
// Launch
// ---------------------------------------------------------------------------
extern "C" void kernel_launch(void* const* d_in, const int* in_sizes, int n_in,
                              void* d_out, int out_size)
{
    const float* x      = (const float*)d_in[0];
    const float* Wl     = (const float*)d_in[1];
    const float* bl     = (const float*)d_in[2];
    const float* Wr     = (const float*)d_in[3];
    const float* br     = (const float*)d_in[4];
    const float* conv_w = (const float*)d_in[5];
    const float* conv_b = (const float*)d_in[6];
    const float* Wa     = (const float*)d_in[7];
    const float* ba     = (const float*)d_in[8];
    const float* Wi     = (const float*)d_in[9];
    const float* bi     = (const float*)d_in[10];
    const float* lam    = (const float*)d_in[11];
    const float* Wo     = (const float*)d_in[12];
    const float* bo     = (const float*)d_in[13];
    float* out = (float*)d_out;

    __half *p_wlh, *p_wrh, *p_wah, *p_wih, *p_woh;
    __half *p_lefth, *p_rinh, *p_convh, *p_rh, *p_dh, *p_yh;
    float *p_ra, *p_lamc;
    cudaGetSymbolAddress((void**)&p_wlh,   g_wlh);
    cudaGetSymbolAddress((void**)&p_wrh,   g_wrh);
    cudaGetSymbolAddress((void**)&p_wah,   g_wah);
    cudaGetSymbolAddress((void**)&p_wih,   g_wih);
    cudaGetSymbolAddress((void**)&p_woh,   g_woh);
    cudaGetSymbolAddress((void**)&p_lefth, g_lefth);
    cudaGetSymbolAddress((void**)&p_rinh,  g_rinh);
    cudaGetSymbolAddress((void**)&p_convh, g_convh);
    cudaGetSymbolAddress((void**)&p_rh,    g_rh);
    cudaGetSymbolAddress((void**)&p_dh,    g_dh);
    cudaGetSymbolAddress((void**)&p_yh,    g_yh);
    cudaGetSymbolAddress((void**)&p_ra,    g_ra);
    cudaGetSymbolAddress((void**)&p_lamc,  g_lamc);

    cudaFuncSetAttribute((const void*)gemm_h<0,0>, cudaFuncAttributeMaxDynamicSharedMemorySize, SM_BYTES);
    cudaFuncSetAttribute((const void*)gemm_h<2,0>, cudaFuncAttributeMaxDynamicSharedMemorySize, SM_BYTES);
    cudaFuncSetAttribute((const void*)gemm_h<3,0>, cudaFuncAttributeMaxDynamicSharedMemorySize, SM_BYTES);
    cudaFuncSetAttribute((const void*)gemm_h<4,1>, cudaFuncAttributeMaxDynamicSharedMemorySize, SM_BYTES);

    dim3 blk(256);
    dim3 gridHx2(2 * HID / 128, MROWS / 128);   // fused Wl+Wr
    dim3 gridH(HID / 128, MROWS / 128);
    dim3 gridO(OUTD / 128, MROWS / 128);
    int sc_blocks = (BATCH * NCHUNK * HID) / 512;   // 2 h per thread

    // consolidated prep: weights transpose + lamc
    prep_all<<<NB_PREP, blk>>>(Wl, Wr, Wa, Wi, Wo, lam);

    // fused: left = gelu(x@Wl+bl) -> f16 ; rin = x@Wr+br -> f16
    // (A = fp32 x, converted in staging)
    gemm_h<4,1><<<gridHx2, blk, SM_BYTES>>>(nullptr, x, p_wlh, bl, nullptr, p_lefth,
                                            MROWS, HID, IND,
                                            nullptr, nullptr, nullptr, nullptr,
                                            p_wrh, br, p_rinh);

    // causal depthwise conv -> f16
    conv_kernel<<<(MROWS * HID) / 2048, blk>>>(conv_w, conv_b);

    // r = sigmoid(conv@Wa+ba) -> f16
    gemm_h<2,0><<<gridH, blk, SM_BYTES>>>(p_convh, nullptr, p_wah, ba, nullptr, p_rh,
                                          MROWS, HID, HID,
                                          nullptr, nullptr, nullptr, nullptr,
                                          nullptr, nullptr, nullptr);
    // Wi-GEMM + fused gate epilogue: a -> f32, drive -> f16
    gemm_h<3,0><<<gridH, blk, SM_BYTES>>>(p_convh, nullptr, p_wih, bi, nullptr, p_dh,
                                          MROWS, HID, HID,
                                          p_rh, p_convh, p_lamc, p_ra,
                                          nullptr, nullptr, nullptr);

    // chunked scan + y = f16(left*h)
    scan_pass1<<<sc_blocks, blk>>>();
    scan_pass3<<<sc_blocks, blk>>>();

    // out = y@Wo + bo
    gemm_h<0,0><<<gridO, blk, SM_BYTES>>>(p_yh, nullptr, p_woh, bo, out, nullptr,
                                          MROWS, OUTD, HID,
                                          nullptr, nullptr, nullptr, nullptr,
                                          nullptr, nullptr, nullptr);
}

// round 16
// speedup vs baseline: 1.1794x; 1.1794x over previous
#include <cuda_runtime.h>
#include <cuda_fp16.h>
#include <cstdint>
#include <math.h>

// Problem dims (fixed by the reference)
#define HID   2560
#define SEQ   2048
#define BATCH 4
#define IND   2048
#define OUTD  2048
#define MROWS (BATCH * SEQ)   // 8192

#define NCHUNK 16
#define CLEN   (SEQ / NCHUNK) // 128

// ---------------------------------------------------------------------------
// Scratch (device globals -- no cudaMalloc allowed)
// ---------------------------------------------------------------------------
__device__ __half g_xh   [(size_t)MROWS * IND];   // fp16 x
__device__ __half g_wlh  [(size_t)IND * HID];     // fp16 Wl^T [HID][IND]
__device__ __half g_wrh  [(size_t)IND * HID];     // fp16 Wr^T
__device__ __half g_wah  [(size_t)HID * HID];     // fp16 Wa^T
__device__ __half g_wih  [(size_t)HID * HID];     // fp16 Wi^T
__device__ __half g_woh  [(size_t)HID * OUTD];    // fp16 Wo^T [OUTD][HID]
__device__ __half g_lefth[(size_t)MROWS * HID];   // fp16 gelu output
__device__ __half g_rinh [(size_t)MROWS * HID];   // fp16 x@Wr+br
__device__ __half g_convh[(size_t)MROWS * HID];   // fp16 conv output
__device__ __half g_rh   [(size_t)MROWS * HID];   // fp16 r = sigmoid(conv@Wa+ba)
__device__ __half g_dh   [(size_t)MROWS * HID];   // fp16 drive
__device__ __half g_yh   [(size_t)MROWS * HID];   // fp16 left*h
__device__ float  g_ra   [(size_t)MROWS * HID];   // a (fp32)
__device__ float  g_cp   [BATCH * NCHUNK * HID];
__device__ float  g_ch   [BATCH * NCHUNK * HID];
__device__ float  g_lamc [HID];                   // -8*softplus(-lam)

// ---------------------------------------------------------------------------
// helpers
// ---------------------------------------------------------------------------
__device__ __forceinline__ uint32_t smem_u32(const void* p) {
    uint32_t a;
    asm("{ .reg .u64 t; cvta.to.shared.u64 t, %1; cvt.u32.u64 %0, t; }" : "=r"(a) : "l"(p));
    return a;
}
__device__ __forceinline__ void cp16(uint32_t dst, const void* src) {
    asm volatile("cp.async.cg.shared.global [%0], [%1], 16;" :: "r"(dst), "l"(src));
}
#define CP_COMMIT() asm volatile("cp.async.commit_group;" ::: "memory")
#define CP_WAIT1()  asm volatile("cp.async.wait_group 1;" ::: "memory")

__device__ __forceinline__ void ldsm_x4(uint32_t* r, uint32_t addr) {
    asm volatile("ldmatrix.sync.aligned.m8n8.x4.shared.b16 {%0,%1,%2,%3}, [%4];"
                 : "=r"(r[0]), "=r"(r[1]), "=r"(r[2]), "=r"(r[3]) : "r"(addr));
}
__device__ __forceinline__ void mma16(float* d, const uint32_t* a, const uint32_t* b) {
    asm volatile(
        "mma.sync.aligned.m16n8k16.row.col.f32.f16.f16.f32 "
        "{%0,%1,%2,%3},{%4,%5,%6,%7},{%8,%9},{%0,%1,%2,%3};\n"
        : "+f"(d[0]), "+f"(d[1]), "+f"(d[2]), "+f"(d[3])
        : "r"(a[0]), "r"(a[1]), "r"(a[2]), "r"(a[3]),
          "r"(b[0]), "r"(b[1]));
}

__device__ __forceinline__ float sqrt_ap(float x) {
    float y;
    asm("sqrt.approx.f32 %0, %1;" : "=f"(y) : "f"(x));
    return y;
}
__device__ __forceinline__ float tanh_ap(float x) {
    float y;
    asm("tanh.approx.f32 %0, %1;" : "=f"(y) : "f"(x));
    return y;
}
// sigmoid(v) = 0.5*tanh(v/2) + 0.5  (1 MUFU)
__device__ __forceinline__ float sigmoid_f(float v) {
    return fmaf(0.5f, tanh_ap(0.5f * v), 0.5f);
}
// gelu tanh form directly: 0.5*v*(1+tanh(c))  (1 MUFU)
__device__ __forceinline__ float gelu_f(float v) {
    float c = 0.7978845608028654f * (v + 0.044715f * v * v * v);
    return 0.5f * v * (1.0f + tanh_ap(c));
}

// ---------------------------------------------------------------------------
// fp16 tensor-core GEMM: C = act(A[M,K] @ Bt[N,K]^T + bias), fp32 accumulate.
// A, B fp16 (B pre-transposed to [N][K]). CTA 128x128, 256 threads, 8 warps
// (2x4), warp tile 64x32, mma m16n8k16. k-chunk 64 (128B SW128 rows),
// 3-stage cp.async pipeline. Both operands via ldmatrix.x4. 2 CTAs/SM.
// ACT: 0 none->C(f32),
//      2 sigmoid->Ch(f16),
//      3 sigmoid + fused RG-LRU gate: reads Rbuf(f16)/Ubuf(f16),
//        writes a->Aout(f32), drive->Ch(f16),
//      4 dual: grid.x first half gelu->Ch(f16), second half none->Ch2(f16)
//        using B2/bias2.
// smem: A stages [3][128][128B] @0, B stages same @49152. Total 96KB.
// ---------------------------------------------------------------------------
#define SMB_OFF 49152
#define SM_BYTES 98304

template <int ACT>
__global__ void __launch_bounds__(256, 2)
gemm_h(const __half* __restrict__ A, const __half* __restrict__ B,
       const float* __restrict__ bias, float* __restrict__ C,
       __half* __restrict__ Ch,
       int M, int N, int K,
       const __half* __restrict__ Rbuf, const __half* __restrict__ Ubuf,
       const float* __restrict__ lamc, float* __restrict__ Aout,
       const __half* B2, const float* bias2, __half* Ch2)
{
    extern __shared__ char sm[];
    const int tid  = threadIdx.x;
    const int lane = tid & 31;
    const int warp = tid >> 5;
    const int wm   = (warp >> 2) * 64;
    const int wn   = (warp & 3) * 32;
    const int bM   = blockIdx.y * 128;
    const uint32_t smb = smem_u32(sm);
    const int NK = K >> 6;            // k-chunk 64

    int bN;
    int act = ACT;
    if (ACT == 4) {
        int half_ = gridDim.x >> 1;
        if (blockIdx.x >= half_) {
            B = B2; bias = bias2; Ch = Ch2; act = 0;
            bN = (blockIdx.x - half_) * 128;
        } else {
            act = 1;
            bN = blockIdx.x * 128;
        }
    } else {
        bN = blockIdx.x * 128;
    }

    float acc[4][4][4];
#pragma unroll
    for (int i = 0; i < 4; i++)
#pragma unroll
        for (int j = 0; j < 4; j++)
#pragma unroll
            for (int k = 0; k < 4; k++) acc[i][j][k] = 0.0f;

    auto load_stage = [&](int kc, int s) {
        const int k0 = kc << 6;
#pragma unroll
        for (int i = 0; i < 4; i++) {
            int idx = tid + (i << 8);
            int r = idx >> 3, c = idx & 7;
            uint32_t o = (uint32_t)(r * 128 + c * 16);
            o ^= (uint32_t)((r & 7) << 4);
            cp16(smb + (uint32_t)s * 16384u + o,
                 A + (size_t)(bM + r) * K + k0 + (c << 3));
        }
#pragma unroll
        for (int i = 0; i < 4; i++) {
            int idx = tid + (i << 8);
            int r = idx >> 3, c = idx & 7;
            uint32_t o = (uint32_t)(r * 128 + c * 16);
            o ^= (uint32_t)((r & 7) << 4);
            cp16(smb + SMB_OFF + (uint32_t)s * 16384u + o,
                 B + (size_t)(bN + r) * K + k0 + (c << 3));
        }
    };

    load_stage(0, 0); CP_COMMIT();
    load_stage(1, 1); CP_COMMIT();

    const int jmat = lane >> 3;       // 0..3
    const int r8   = lane & 7;

    int stage = 0;
    for (int kc = 0; kc < NK; kc++) {
        CP_WAIT1();
        __syncthreads();
        if (kc + 2 < NK) load_stage(kc + 2, (stage + 2) % 3);
        CP_COMMIT();

        const uint32_t aBase = smb + (uint32_t)stage * 16384u;
        const uint32_t bBase = smb + SMB_OFF + (uint32_t)stage * 16384u;

#pragma unroll
        for (int ks = 0; ks < 4; ks++) {   // 4 k-steps of 16 halfs (32B)
            uint32_t af[4][4];
#pragma unroll
            for (int mt = 0; mt < 4; mt++) {
                int row = wm + mt * 16 + ((jmat & 1) << 3) + r8;
                uint32_t o = (uint32_t)(row * 128 + ks * 32 + ((jmat >> 1) << 4));
                o ^= (uint32_t)(r8 << 4);
                ldsm_x4(af[mt], aBase + o);
            }
            uint32_t bf[4][2];
#pragma unroll
            for (int p = 0; p < 2; p++) {
                int nrow = wn + p * 16 + ((jmat >> 1) << 3) + r8;
                uint32_t o = (uint32_t)(nrow * 128 + ks * 32 + ((jmat & 1) << 4));
                o ^= (uint32_t)(r8 << 4);
                uint32_t t[4];
                ldsm_x4(t, bBase + o);
                bf[p * 2 + 0][0] = t[0]; bf[p * 2 + 0][1] = t[1];
                bf[p * 2 + 1][0] = t[2]; bf[p * 2 + 1][1] = t[3];
            }
#pragma unroll
            for (int mt = 0; mt < 4; mt++)
#pragma unroll
                for (int nt = 0; nt < 4; nt++)
                    mma16(acc[mt][nt], af[mt], bf[nt]);
        }
        stage = (stage + 1) % 3;
    }

    // --------------------------- epilogue ---------------------------------
#pragma unroll
    for (int mt = 0; mt < 4; mt++) {
        int row0 = bM + wm + mt * 16 + (lane >> 2);
#pragma unroll
        for (int nt = 0; nt < 4; nt++) {
            int col = bN + wn + nt * 8 + ((lane & 3) << 1);
            float b0 = bias[col], b1 = bias[col + 1];
            if (ACT == 3) {
                float lc0 = lamc[col], lc1 = lamc[col + 1];
#pragma unroll
                for (int rr = 0; rr < 2; rr++) {
                    size_t idx = (size_t)(row0 + rr * 8) * N + col;
                    float i0 = sigmoid_f(acc[mt][nt][rr * 2 + 0] + b0);
                    float i1 = sigmoid_f(acc[mt][nt][rr * 2 + 1] + b1);
                    __half2 rh = *(const __half2*)(Rbuf + idx);
                    __half2 uh = *(const __half2*)(Ubuf + idx);
                    float a0 = __expf(lc0 * __half2float(__low2half(rh)));
                    float a1 = __expf(lc1 * __half2float(__high2half(rh)));
                    float be0 = sqrt_ap(fmaxf(1.0f - a0 * a0, 1e-12f));
                    float be1 = sqrt_ap(fmaxf(1.0f - a1 * a1, 1e-12f));
                    float d0 = be0 * i0 * __half2float(__low2half(uh));
                    float d1 = be1 * i1 * __half2float(__high2half(uh));
                    *(float2*)(Aout + idx) = make_float2(a0, a1);
                    *(__half2*)(Ch + idx) = __floats2half2_rn(d0, d1);
                }
            } else if (ACT == 4) {
#pragma unroll
                for (int rr = 0; rr < 2; rr++) {
                    float v0 = acc[mt][nt][rr * 2 + 0] + b0;
                    float v1 = acc[mt][nt][rr * 2 + 1] + b1;
                    size_t idx = (size_t)(row0 + rr * 8) * N + col;
                    if (act == 1) { v0 = gelu_f(v0); v1 = gelu_f(v1); }
                    *(__half2*)(Ch + idx) = __floats2half2_rn(v0, v1);
                }
            } else if (ACT == 2) {
#pragma unroll
                for (int rr = 0; rr < 2; rr++) {
                    float v0 = sigmoid_f(acc[mt][nt][rr * 2 + 0] + b0);
                    float v1 = sigmoid_f(acc[mt][nt][rr * 2 + 1] + b1);
                    *(__half2*)(Ch + (size_t)(row0 + rr * 8) * N + col) =
                        __floats2half2_rn(v0, v1);
                }
            } else {
#pragma unroll
                for (int rr = 0; rr < 2; rr++) {
                    float v0 = acc[mt][nt][rr * 2 + 0] + b0;
                    float v1 = acc[mt][nt][rr * 2 + 1] + b1;
                    *(float2*)(C + (size_t)(row0 + rr * 8) * N + col) = make_float2(v0, v1);
                }
            }
        }
    }
}

// ---------------------------------------------------------------------------
// One 32x32 transpose+convert tile: dst[N][K] = half(src[K][N])
// ---------------------------------------------------------------------------
__device__ __forceinline__ void tr_tile(const float* __restrict__ src,
                                        __half* __restrict__ dst,
                                        int K, int N, int bx, int by)
{
    __shared__ float t[32][33];
    int k0 = by * 32, n0 = bx * 32;
    int tx = threadIdx.x & 31, ty = threadIdx.x >> 5;
#pragma unroll
    for (int i = 0; i < 32; i += 8)
        t[ty + i][tx] = src[(size_t)(k0 + ty + i) * N + n0 + tx];
    __syncthreads();
#pragma unroll
    for (int i = 0; i < 32; i += 8)
        dst[(size_t)(n0 + ty + i) * K + k0 + tx] = __float2half_rn(t[tx][ty + i]);
}

// ---------------------------------------------------------------------------
// Consolidated prep: 5 weight transposes + lamc + x->fp16, one launch.
// Block segments: Wl 5120, Wr 5120, Wa 6400, Wi 6400, Wo 5120, lamc 10,
// then x-convert blocks (1024 elems each).
// ---------------------------------------------------------------------------
#define NB_WL 5120   // 80*64
#define NB_WA 6400   // 80*80
#define NB_WO 5120   // 64*80
#define NB_W   (NB_WL*2 + NB_WA*2 + NB_WO + 10)
#define NB_X   ((MROWS * IND) / 1024)
#define NB_PREP (NB_W + NB_X)

__global__ void prep_all(const float* __restrict__ Wl, const float* __restrict__ Wr,
                         const float* __restrict__ Wa, const float* __restrict__ Wi,
                         const float* __restrict__ Wo, const float* __restrict__ lam,
                         const float* __restrict__ x)
{
    int id = blockIdx.x;
    if (id < NB_WL) {
        tr_tile(Wl, g_wlh, IND, HID, id % 80, id / 80);
    } else if (id < 2 * NB_WL) {
        id -= NB_WL;
        tr_tile(Wr, g_wrh, IND, HID, id % 80, id / 80);
    } else if (id < 2 * NB_WL + NB_WA) {
        id -= 2 * NB_WL;
        tr_tile(Wa, g_wah, HID, HID, id % 80, id / 80);
    } else if (id < 2 * NB_WL + 2 * NB_WA) {
        id -= 2 * NB_WL + NB_WA;
        tr_tile(Wi, g_wih, HID, HID, id % 80, id / 80);
    } else if (id < 2 * NB_WL + 2 * NB_WA + NB_WO) {
        id -= 2 * NB_WL + 2 * NB_WA;
        tr_tile(Wo, g_woh, HID, OUTD, id % 64, id / 64);
    } else if (id < NB_W) {
        id -= 2 * NB_WL + 2 * NB_WA + NB_WO;
        int h = id * 256 + threadIdx.x;
        if (h < HID) g_lamc[h] = -8.0f * log1pf(__expf(-lam[h]));
    } else {
        id -= NB_W;
        int i = (id * 256 + threadIdx.x) * 4;
        float4 v = *(const float4*)(x + i);
        *(__half2*)(g_xh + i)     = __floats2half2_rn(v.x, v.y);
        *(__half2*)(g_xh + i + 2) = __floats2half2_rn(v.z, v.w);
    }
}

// ---------------------------------------------------------------------------
// Causal depthwise conv1d (width 4, left pad 3); fp16 in/out, 8 elems/thread
// (proven R8 version)
// ---------------------------------------------------------------------------
__global__ void conv_kernel(const float* __restrict__ w, const float* __restrict__ cb)
{
    int i = (blockIdx.x * blockDim.x + threadIdx.x) * 8;
    int h = i % HID;
    int s = (i / HID) % SEQ;
    const __half* base = g_rinh + (size_t)i;
    float acc[8];
#pragma unroll
    for (int e = 0; e < 8; e += 4) {
        float4 b4 = *(const float4*)(cb + h + e);
        acc[e] = b4.x; acc[e + 1] = b4.y; acc[e + 2] = b4.z; acc[e + 3] = b4.w;
    }
#pragma unroll
    for (int k = 0; k < 4; k++) {
        int t = s - 3 + k;
        if (t >= 0) {
            uint4 vv = *(const uint4*)(base + (long)(k - 3) * HID);
            const __half2* vh = (const __half2*)&vv;
#pragma unroll
            for (int e = 0; e < 8; e += 4) {
                float4 wv = *(const float4*)(w + k * HID + h + e);
                __half2 p0 = vh[e / 2], p1 = vh[e / 2 + 1];
                acc[e + 0] = fmaf(wv.x, __half2float(__low2half(p0)),  acc[e + 0]);
                acc[e + 1] = fmaf(wv.y, __half2float(__high2half(p0)), acc[e + 1]);
                acc[e + 2] = fmaf(wv.z, __half2float(__low2half(p1)),  acc[e + 2]);
                acc[e + 3] = fmaf(wv.w, __half2float(__high2half(p1)), acc[e + 3]);
            }
        }
    }
    uint4 ov;
    __half2* oh = (__half2*)&ov;
    oh[0] = __floats2half2_rn(acc[0], acc[1]);
    oh[1] = __floats2half2_rn(acc[2], acc[3]);
    oh[2] = __floats2half2_rn(acc[4], acc[5]);
    oh[3] = __floats2half2_rn(acc[6], acc[7]);
    *(uint4*)(g_convh + i) = ov;
}

// ---------------------------------------------------------------------------
// Chunked scan (2 passes), chunk length 128, 16 chunks/sequence.
// 2 h-channels per thread (a: f32, drive: f16). (Proven R12 form.)
// ---------------------------------------------------------------------------
__global__ void scan_pass1()
{
    int idx = (blockIdx.x * blockDim.x + threadIdx.x) * 2;  // over B*NCHUNK*HID
    int h = idx % HID;
    int t = idx / HID;
    int c = t % NCHUNK;
    int b = t / NCHUNK;
    size_t base = ((size_t)b * SEQ + (size_t)c * CLEN) * HID + h;
    float2 P = make_float2(1.0f, 1.0f), hs = make_float2(0.0f, 0.0f);
#pragma unroll 4
    for (int s = 0; s < CLEN; s++) {
        size_t o = base + (size_t)s * HID;
        float2 a = *(const float2*)(g_ra + o);
        __half2 dh = *(const __half2*)(g_dh + o);
        P.x *= a.x; P.y *= a.y;
        hs.x = fmaf(a.x, hs.x, __half2float(__low2half(dh)));
        hs.y = fmaf(a.y, hs.y, __half2float(__high2half(dh)));
    }
    size_t oo = ((size_t)b * NCHUNK + c) * HID + h;
    *(float2*)(g_cp + oo) = P;
    *(float2*)(g_ch + oo) = hs;
}

__global__ void scan_pass3()
{
    int idx = (blockIdx.x * blockDim.x + threadIdx.x) * 2;
    int h = idx % HID;
    int t = idx / HID;
    int c = t % NCHUNK;
    int b = t / NCHUNK;
    // stitch: fold chunk summaries 0..c-1
    float2 hin = make_float2(0.0f, 0.0f);
    for (int cc = 0; cc < c; cc++) {
        size_t oo = ((size_t)b * NCHUNK + cc) * HID + h;
        float2 p = *(const float2*)(g_cp + oo);
        float2 hh = *(const float2*)(g_ch + oo);
        hin.x = fmaf(p.x, hin.x, hh.x);
        hin.y = fmaf(p.y, hin.y, hh.y);
    }
    size_t base = ((size_t)b * SEQ + (size_t)c * CLEN) * HID + h;
    float2 hs = hin;
#pragma unroll 4
    for (int s = 0; s < CLEN; s++) {
        size_t o = base + (size_t)s * HID;
        float2 a = *(const float2*)(g_ra + o);
        __half2 dh = *(const __half2*)(g_dh + o);
        __half2 lh = *(const __half2*)(g_lefth + o);
        hs.x = fmaf(a.x, hs.x, __half2float(__low2half(dh)));
        hs.y = fmaf(a.y, hs.y, __half2float(__high2half(dh)));
        *(__half2*)(g_yh + o) =
            __floats2half2_rn(__half2float(__low2half(lh)) * hs.x,
                              __half2float(__high2half(lh)) * hs.y);
    }
}

// ---------------------------------------------------------------------------
// Launch
// ---------------------------------------------------------------------------
extern "C" void kernel_launch(void* const* d_in, const int* in_sizes, int n_in,
                              void* d_out, int out_size)
{
    const float* x      = (const float*)d_in[0];
    const float* Wl     = (const float*)d_in[1];
    const float* bl     = (const float*)d_in[2];
    const float* Wr     = (const float*)d_in[3];
    const float* br     = (const float*)d_in[4];
    const float* conv_w = (const float*)d_in[5];
    const float* conv_b = (const float*)d_in[6];
    const float* Wa     = (const float*)d_in[7];
    const float* ba     = (const float*)d_in[8];
    const float* Wi     = (const float*)d_in[9];
    const float* bi     = (const float*)d_in[10];
    const float* lam    = (const float*)d_in[11];
    const float* Wo     = (const float*)d_in[12];
    const float* bo     = (const float*)d_in[13];
    float* out = (float*)d_out;

    __half *p_wlh, *p_wrh, *p_wah, *p_wih, *p_woh;
    __half *p_lefth, *p_rinh, *p_convh, *p_rh, *p_dh, *p_yh, *p_xh;
    float *p_ra, *p_lamc;
    cudaGetSymbolAddress((void**)&p_xh,    g_xh);
    cudaGetSymbolAddress((void**)&p_wlh,   g_wlh);
    cudaGetSymbolAddress((void**)&p_wrh,   g_wrh);
    cudaGetSymbolAddress((void**)&p_wah,   g_wah);
    cudaGetSymbolAddress((void**)&p_wih,   g_wih);
    cudaGetSymbolAddress((void**)&p_woh,   g_woh);
    cudaGetSymbolAddress((void**)&p_lefth, g_lefth);
    cudaGetSymbolAddress((void**)&p_rinh,  g_rinh);
    cudaGetSymbolAddress((void**)&p_convh, g_convh);
    cudaGetSymbolAddress((void**)&p_rh,    g_rh);
    cudaGetSymbolAddress((void**)&p_dh,    g_dh);
    cudaGetSymbolAddress((void**)&p_yh,    g_yh);
    cudaGetSymbolAddress((void**)&p_ra,    g_ra);
    cudaGetSymbolAddress((void**)&p_lamc,  g_lamc);

    cudaFuncSetAttribute(gemm_h<0>, cudaFuncAttributeMaxDynamicSharedMemorySize, SM_BYTES);
    cudaFuncSetAttribute(gemm_h<2>, cudaFuncAttributeMaxDynamicSharedMemorySize, SM_BYTES);
    cudaFuncSetAttribute(gemm_h<3>, cudaFuncAttributeMaxDynamicSharedMemorySize, SM_BYTES);
    cudaFuncSetAttribute(gemm_h<4>, cudaFuncAttributeMaxDynamicSharedMemorySize, SM_BYTES);

    dim3 blk(256);
    dim3 gridHx2(2 * HID / 128, MROWS / 128);   // fused Wl+Wr
    dim3 gridH(HID / 128, MROWS / 128);
    dim3 gridO(OUTD / 128, MROWS / 128);
    int sc_blocks = (BATCH * NCHUNK * HID) / 512;   // 2 h per thread

    // consolidated prep: weights transpose + lamc + x->fp16
    prep_all<<<NB_PREP, blk>>>(Wl, Wr, Wa, Wi, Wo, lam, x);

    // fused: left = gelu(x@Wl+bl) -> f16 ; rin = x@Wr+br -> f16
    gemm_h<4><<<gridHx2, blk, SM_BYTES>>>(p_xh, p_wlh, bl, nullptr, p_lefth,
                                          MROWS, HID, IND,
                                          nullptr, nullptr, nullptr, nullptr,
                                          p_wrh, br, p_rinh);

    // causal depthwise conv -> f16
    conv_kernel<<<(MROWS * HID) / 2048, blk>>>(conv_w, conv_b);

    // r = sigmoid(conv@Wa+ba) -> f16
    gemm_h<2><<<gridH, blk, SM_BYTES>>>(p_convh, p_wah, ba, nullptr, p_rh,
                                        MROWS, HID, HID,
                                        nullptr, nullptr, nullptr, nullptr,
                                        nullptr, nullptr, nullptr);
    // Wi-GEMM + fused gate epilogue: a -> f32, drive -> f16
    gemm_h<3><<<gridH, blk, SM_BYTES>>>(p_convh, p_wih, bi, nullptr, p_dh,
                                        MROWS, HID, HID,
                                        p_rh, p_convh, p_lamc, p_ra,
                                        nullptr, nullptr, nullptr);

    // chunked scan + y = f16(left*h)
    scan_pass1<<<sc_blocks, blk>>>();
    scan_pass3<<<sc_blocks, blk>>>();

    // out = y@Wo + bo
    gemm_h<0><<<gridO, blk, SM_BYTES>>>(p_yh, p_woh, bo, out, nullptr,
                                        MROWS, OUTD, HID,
                                        nullptr, nullptr, nullptr, nullptr,
                                        nullptr, nullptr, nullptr);
}

// round 17
// speedup vs baseline: 1.1900x; 1.0090x over previous
#include <cuda_runtime.h>
#include <cuda_fp16.h>
#include <cstdint>
#include <math.h>

// Problem dims (fixed by the reference)
#define HID   2560
#define SEQ   2048
#define BATCH 4
#define IND   2048
#define OUTD  2048
#define MROWS (BATCH * SEQ)   // 8192

#define NCHUNK 16
#define CLEN   (SEQ / NCHUNK) // 128

// ---------------------------------------------------------------------------
// Scratch (device globals -- no cudaMalloc allowed)
// ---------------------------------------------------------------------------
__device__ __half g_xh   [(size_t)MROWS * IND];   // fp16 x
__device__ __half g_wlh  [(size_t)IND * HID];     // fp16 Wl^T [HID][IND]
__device__ __half g_wrh  [(size_t)IND * HID];     // fp16 Wr^T
__device__ __half g_wah  [(size_t)HID * HID];     // fp16 Wa^T
__device__ __half g_wih  [(size_t)HID * HID];     // fp16 Wi^T
__device__ __half g_woh  [(size_t)HID * OUTD];    // fp16 Wo^T [OUTD][HID]
__device__ __half g_lefth[(size_t)MROWS * HID];   // fp16 gelu output
__device__ __half g_rinh [(size_t)MROWS * HID];   // fp16 x@Wr+br
__device__ __half g_convh[(size_t)MROWS * HID];   // fp16 conv output
__device__ __half g_rh   [(size_t)MROWS * HID];   // fp16 r = sigmoid(conv@Wa+ba)
__device__ __half g_dh   [(size_t)MROWS * HID];   // fp16 drive
__device__ __half g_yh   [(size_t)MROWS * HID];   // fp16 left*h
__device__ float  g_ra   [(size_t)MROWS * HID];   // a (fp32)
__device__ float  g_cp   [BATCH * NCHUNK * HID];
__device__ float  g_ch   [BATCH * NCHUNK * HID];
__device__ float  g_lamc [HID];                   // -8*softplus(-lam)

// ---------------------------------------------------------------------------
// helpers
// ---------------------------------------------------------------------------
__device__ __forceinline__ uint32_t smem_u32(const void* p) {
    uint32_t a;
    asm("{ .reg .u64 t; cvta.to.shared.u64 t, %1; cvt.u32.u64 %0, t; }" : "=r"(a) : "l"(p));
    return a;
}
__device__ __forceinline__ void cp16(uint32_t dst, const void* src) {
    asm volatile("cp.async.cg.shared.global [%0], [%1], 16;" :: "r"(dst), "l"(src));
}
#define CP_COMMIT() asm volatile("cp.async.commit_group;" ::: "memory")
#define CP_WAIT1()  asm volatile("cp.async.wait_group 1;" ::: "memory")

__device__ __forceinline__ void ldsm_x4(uint32_t* r, uint32_t addr) {
    asm volatile("ldmatrix.sync.aligned.m8n8.x4.shared.b16 {%0,%1,%2,%3}, [%4];"
                 : "=r"(r[0]), "=r"(r[1]), "=r"(r[2]), "=r"(r[3]) : "r"(addr));
}
__device__ __forceinline__ void mma16(float* d, const uint32_t* a, const uint32_t* b) {
    asm volatile(
        "mma.sync.aligned.m16n8k16.row.col.f32.f16.f16.f32 "
        "{%0,%1,%2,%3},{%4,%5,%6,%7},{%8,%9},{%0,%1,%2,%3};\n"
        : "+f"(d[0]), "+f"(d[1]), "+f"(d[2]), "+f"(d[3])
        : "r"(a[0]), "r"(a[1]), "r"(a[2]), "r"(a[3]),
          "r"(b[0]), "r"(b[1]));
}

__device__ __forceinline__ float sqrt_ap(float x) {
    float y;
    asm("sqrt.approx.f32 %0, %1;" : "=f"(y) : "f"(x));
    return y;
}
__device__ __forceinline__ float tanh_ap(float x) {
    float y;
    asm("tanh.approx.f32 %0, %1;" : "=f"(y) : "f"(x));
    return y;
}
// sigmoid(v) = 0.5*tanh(v/2) + 0.5  (1 MUFU)
__device__ __forceinline__ float sigmoid_f(float v) {
    return fmaf(0.5f, tanh_ap(0.5f * v), 0.5f);
}
// gelu tanh form directly: 0.5*v*(1+tanh(c))  (1 MUFU)
__device__ __forceinline__ float gelu_f(float v) {
    float c = 0.7978845608028654f * (v + 0.044715f * v * v * v);
    return 0.5f * v * (1.0f + tanh_ap(c));
}

// ---------------------------------------------------------------------------
// fp16 tensor-core GEMM: C = act(A[M,K] @ Bt[N,K]^T + bias), fp32 accumulate.
// A, B fp16 (B pre-transposed to [N][K]). CTA 128x128, 256 threads, 8 warps
// (2x4), warp tile 64x32, mma m16n8k16. k-chunk 64 (128B SW128 rows),
// 3-stage cp.async pipeline. Both operands via ldmatrix.x4. 2 CTAs/SM.
// ACT: 0 none->C(f32),
//      2 sigmoid->Ch(f16),
//      3 sigmoid + fused RG-LRU gate: reads Rbuf(f16)/Ubuf(f16),
//        writes a->Aout(f32), drive->Ch(f16),
//      4 dual: grid.x first half gelu->Ch(f16), second half none->Ch2(f16)
//        using B2/bias2.
// smem: A stages [3][128][128B] @0, B stages same @49152. Total 96KB.
// ---------------------------------------------------------------------------
#define SMB_OFF 49152
#define SM_BYTES 98304

template <int ACT>
__global__ void __launch_bounds__(256, 2)
gemm_h(const __half* __restrict__ A, const __half* __restrict__ B,
       const float* __restrict__ bias, float* __restrict__ C,
       __half* __restrict__ Ch,
       int M, int N, int K,
       const __half* __restrict__ Rbuf, const __half* __restrict__ Ubuf,
       const float* __restrict__ lamc, float* __restrict__ Aout,
       const __half* B2, const float* bias2, __half* Ch2)
{
    extern __shared__ char sm[];
    const int tid  = threadIdx.x;
    const int lane = tid & 31;
    const int warp = tid >> 5;
    const int wm   = (warp >> 2) * 64;
    const int wn   = (warp & 3) * 32;
    const int bM   = blockIdx.y * 128;
    const uint32_t smb = smem_u32(sm);
    const int NK = K >> 6;            // k-chunk 64

    int bN;
    int act = ACT;
    if (ACT == 4) {
        int half_ = gridDim.x >> 1;
        if (blockIdx.x >= half_) {
            B = B2; bias = bias2; Ch = Ch2; act = 0;
            bN = (blockIdx.x - half_) * 128;
        } else {
            act = 1;
            bN = blockIdx.x * 128;
        }
    } else {
        bN = blockIdx.x * 128;
    }

    float acc[4][4][4];
#pragma unroll
    for (int i = 0; i < 4; i++)
#pragma unroll
        for (int j = 0; j < 4; j++)
#pragma unroll
            for (int k = 0; k < 4; k++) acc[i][j][k] = 0.0f;

    auto load_stage = [&](int kc, int s) {
        const int k0 = kc << 6;
#pragma unroll
        for (int i = 0; i < 4; i++) {
            int idx = tid + (i << 8);
            int r = idx >> 3, c = idx & 7;
            uint32_t o = (uint32_t)(r * 128 + c * 16);
            o ^= (uint32_t)((r & 7) << 4);
            cp16(smb + (uint32_t)s * 16384u + o,
                 A + (size_t)(bM + r) * K + k0 + (c << 3));
        }
#pragma unroll
        for (int i = 0; i < 4; i++) {
            int idx = tid + (i << 8);
            int r = idx >> 3, c = idx & 7;
            uint32_t o = (uint32_t)(r * 128 + c * 16);
            o ^= (uint32_t)((r & 7) << 4);
            cp16(smb + SMB_OFF + (uint32_t)s * 16384u + o,
                 B + (size_t)(bN + r) * K + k0 + (c << 3));
        }
    };

    load_stage(0, 0); CP_COMMIT();
    load_stage(1, 1); CP_COMMIT();

    const int jmat = lane >> 3;       // 0..3
    const int r8   = lane & 7;

    int stage = 0;
    for (int kc = 0; kc < NK; kc++) {
        CP_WAIT1();
        __syncthreads();
        if (kc + 2 < NK) load_stage(kc + 2, (stage + 2) % 3);
        CP_COMMIT();

        const uint32_t aBase = smb + (uint32_t)stage * 16384u;
        const uint32_t bBase = smb + SMB_OFF + (uint32_t)stage * 16384u;

#pragma unroll
        for (int ks = 0; ks < 4; ks++) {   // 4 k-steps of 16 halfs (32B)
            uint32_t af[4][4];
#pragma unroll
            for (int mt = 0; mt < 4; mt++) {
                int row = wm + mt * 16 + ((jmat & 1) << 3) + r8;
                uint32_t o = (uint32_t)(row * 128 + ks * 32 + ((jmat >> 1) << 4));
                o ^= (uint32_t)(r8 << 4);
                ldsm_x4(af[mt], aBase + o);
            }
            uint32_t bf[4][2];
#pragma unroll
            for (int p = 0; p < 2; p++) {
                int nrow = wn + p * 16 + ((jmat >> 1) << 3) + r8;
                uint32_t o = (uint32_t)(nrow * 128 + ks * 32 + ((jmat & 1) << 4));
                o ^= (uint32_t)(r8 << 4);
                uint32_t t[4];
                ldsm_x4(t, bBase + o);
                bf[p * 2 + 0][0] = t[0]; bf[p * 2 + 0][1] = t[1];
                bf[p * 2 + 1][0] = t[2]; bf[p * 2 + 1][1] = t[3];
            }
#pragma unroll
            for (int mt = 0; mt < 4; mt++)
#pragma unroll
                for (int nt = 0; nt < 4; nt++)
                    mma16(acc[mt][nt], af[mt], bf[nt]);
        }
        stage = (stage + 1) % 3;
    }

    // --------------------------- epilogue ---------------------------------
#pragma unroll
    for (int mt = 0; mt < 4; mt++) {
        int row0 = bM + wm + mt * 16 + (lane >> 2);
#pragma unroll
        for (int nt = 0; nt < 4; nt++) {
            int col = bN + wn + nt * 8 + ((lane & 3) << 1);
            float b0 = bias[col], b1 = bias[col + 1];
            if (ACT == 3) {
                float lc0 = lamc[col], lc1 = lamc[col + 1];
#pragma unroll
                for (int rr = 0; rr < 2; rr++) {
                    size_t idx = (size_t)(row0 + rr * 8) * N + col;
                    float i0 = sigmoid_f(acc[mt][nt][rr * 2 + 0] + b0);
                    float i1 = sigmoid_f(acc[mt][nt][rr * 2 + 1] + b1);
                    __half2 rh = *(const __half2*)(Rbuf + idx);
                    __half2 uh = *(const __half2*)(Ubuf + idx);
                    float a0 = __expf(lc0 * __half2float(__low2half(rh)));
                    float a1 = __expf(lc1 * __half2float(__high2half(rh)));
                    float be0 = sqrt_ap(fmaxf(1.0f - a0 * a0, 1e-12f));
                    float be1 = sqrt_ap(fmaxf(1.0f - a1 * a1, 1e-12f));
                    float d0 = be0 * i0 * __half2float(__low2half(uh));
                    float d1 = be1 * i1 * __half2float(__high2half(uh));
                    *(float2*)(Aout + idx) = make_float2(a0, a1);
                    *(__half2*)(Ch + idx) = __floats2half2_rn(d0, d1);
                }
            } else if (ACT == 4) {
#pragma unroll
                for (int rr = 0; rr < 2; rr++) {
                    float v0 = acc[mt][nt][rr * 2 + 0] + b0;
                    float v1 = acc[mt][nt][rr * 2 + 1] + b1;
                    size_t idx = (size_t)(row0 + rr * 8) * N + col;
                    if (act == 1) { v0 = gelu_f(v0); v1 = gelu_f(v1); }
                    *(__half2*)(Ch + idx) = __floats2half2_rn(v0, v1);
                }
            } else if (ACT == 2) {
#pragma unroll
                for (int rr = 0; rr < 2; rr++) {
                    float v0 = sigmoid_f(acc[mt][nt][rr * 2 + 0] + b0);
                    float v1 = sigmoid_f(acc[mt][nt][rr * 2 + 1] + b1);
                    *(__half2*)(Ch + (size_t)(row0 + rr * 8) * N + col) =
                        __floats2half2_rn(v0, v1);
                }
            } else {
#pragma unroll
                for (int rr = 0; rr < 2; rr++) {
                    float v0 = acc[mt][nt][rr * 2 + 0] + b0;
                    float v1 = acc[mt][nt][rr * 2 + 1] + b1;
                    *(float2*)(C + (size_t)(row0 + rr * 8) * N + col) = make_float2(v0, v1);
                }
            }
        }
    }
}

// ---------------------------------------------------------------------------
// One 32x32 transpose+convert tile: dst[N][K] = half(src[K][N])
// ---------------------------------------------------------------------------
__device__ __forceinline__ void tr_tile(const float* __restrict__ src,
                                        __half* __restrict__ dst,
                                        int K, int N, int bx, int by)
{
    __shared__ float t[32][33];
    int k0 = by * 32, n0 = bx * 32;
    int tx = threadIdx.x & 31, ty = threadIdx.x >> 5;
#pragma unroll
    for (int i = 0; i < 32; i += 8)
        t[ty + i][tx] = src[(size_t)(k0 + ty + i) * N + n0 + tx];
    __syncthreads();
#pragma unroll
    for (int i = 0; i < 32; i += 8)
        dst[(size_t)(n0 + ty + i) * K + k0 + tx] = __float2half_rn(t[tx][ty + i]);
}

// ---------------------------------------------------------------------------
// Consolidated prep: 5 weight transposes + lamc + x->fp16, one launch.
// Block segments: Wl 5120, Wr 5120, Wa 6400, Wi 6400, Wo 5120, lamc 10,
// then x-convert blocks (2048 elems each, 8/thread, uint4 stores).
// ---------------------------------------------------------------------------
#define NB_WL 5120   // 80*64
#define NB_WA 6400   // 80*80
#define NB_WO 5120   // 64*80
#define NB_W   (NB_WL*2 + NB_WA*2 + NB_WO + 10)
#define NB_X   ((MROWS * IND) / 2048)
#define NB_PREP (NB_W + NB_X)

__global__ void prep_all(const float* __restrict__ Wl, const float* __restrict__ Wr,
                         const float* __restrict__ Wa, const float* __restrict__ Wi,
                         const float* __restrict__ Wo, const float* __restrict__ lam,
                         const float* __restrict__ x)
{
    int id = blockIdx.x;
    if (id < NB_WL) {
        tr_tile(Wl, g_wlh, IND, HID, id % 80, id / 80);
    } else if (id < 2 * NB_WL) {
        id -= NB_WL;
        tr_tile(Wr, g_wrh, IND, HID, id % 80, id / 80);
    } else if (id < 2 * NB_WL + NB_WA) {
        id -= 2 * NB_WL;
        tr_tile(Wa, g_wah, HID, HID, id % 80, id / 80);
    } else if (id < 2 * NB_WL + 2 * NB_WA) {
        id -= 2 * NB_WL + NB_WA;
        tr_tile(Wi, g_wih, HID, HID, id % 80, id / 80);
    } else if (id < 2 * NB_WL + 2 * NB_WA + NB_WO) {
        id -= 2 * NB_WL + 2 * NB_WA;
        tr_tile(Wo, g_woh, HID, OUTD, id % 64, id / 64);
    } else if (id < NB_W) {
        id -= 2 * NB_WL + 2 * NB_WA + NB_WO;
        int h = id * 256 + threadIdx.x;
        if (h < HID) g_lamc[h] = -8.0f * log1pf(__expf(-lam[h]));
    } else {
        id -= NB_W;
        int i = (id * 256 + threadIdx.x) * 8;
        float4 v0 = *(const float4*)(x + i);
        float4 v1 = *(const float4*)(x + i + 4);
        uint4 ov;
        __half2* oh = (__half2*)&ov;
        oh[0] = __floats2half2_rn(v0.x, v0.y);
        oh[1] = __floats2half2_rn(v0.z, v0.w);
        oh[2] = __floats2half2_rn(v1.x, v1.y);
        oh[3] = __floats2half2_rn(v1.z, v1.w);
        *(uint4*)(g_xh + i) = ov;
    }
}

// ---------------------------------------------------------------------------
// Causal depthwise conv1d (width 4, left pad 3); fp16 in/out.
// Each thread: 8 h-channels x 8 s-steps with a rolling 4-row data window;
// weights/bias loaded once per thread (amortized 8x vs per-s loading).
// Per-element math identical to the previous version (bias then taps k=0..3).
// ---------------------------------------------------------------------------
__global__ void conv_kernel(const float* __restrict__ w, const float* __restrict__ cb)
{
    int tidg = blockIdx.x * blockDim.x + threadIdx.x;
    const int NH = HID / 8;                 // 320 h-groups
    int h0 = (tidg % NH) * 8;
    int tt = tidg / NH;
    int s0 = (tt % (SEQ / 8)) * 8;
    int b  = tt / (SEQ / 8);

    // weights [4 taps][8 h] and bias[8 h], loaded once
    float wr[4][8];
#pragma unroll
    for (int k = 0; k < 4; k++) {
        float4 a0 = *(const float4*)(w + k * HID + h0);
        float4 a1 = *(const float4*)(w + k * HID + h0 + 4);
        wr[k][0] = a0.x; wr[k][1] = a0.y; wr[k][2] = a0.z; wr[k][3] = a0.w;
        wr[k][4] = a1.x; wr[k][5] = a1.y; wr[k][6] = a1.z; wr[k][7] = a1.w;
    }
    float bs[8];
    {
        float4 b0 = *(const float4*)(cb + h0);
        float4 b1 = *(const float4*)(cb + h0 + 4);
        bs[0] = b0.x; bs[1] = b0.y; bs[2] = b0.z; bs[3] = b0.w;
        bs[4] = b1.x; bs[5] = b1.y; bs[6] = b1.z; bs[7] = b1.w;
    }

    const __half* base = g_rinh + (size_t)b * SEQ * HID + h0;
    __half* outp = g_convh + (size_t)b * SEQ * HID + h0;

    // rolling window: win[k] = row (s-3+k) for the current s
    uint4 win[4];
    uint4 zz = make_uint4(0u, 0u, 0u, 0u);
#pragma unroll
    for (int k = 0; k < 3; k++) {
        int s = s0 - 3 + k;
        win[k] = (s >= 0) ? *(const uint4*)(base + (size_t)s * HID) : zz;
    }
#pragma unroll
    for (int ss = 0; ss < 8; ss++) {
        int s = s0 + ss;
        win[3] = *(const uint4*)(base + (size_t)s * HID);
        float acc[8];
#pragma unroll
        for (int e = 0; e < 8; e++) acc[e] = bs[e];
#pragma unroll
        for (int k = 0; k < 4; k++) {
            const __half2* vh = (const __half2*)&win[k];
#pragma unroll
            for (int p = 0; p < 4; p++) {
                float lo = __half2float(__low2half(vh[p]));
                float hi = __half2float(__high2half(vh[p]));
                acc[2 * p + 0] = fmaf(wr[k][2 * p + 0], lo, acc[2 * p + 0]);
                acc[2 * p + 1] = fmaf(wr[k][2 * p + 1], hi, acc[2 * p + 1]);
            }
        }
        uint4 ov;
        __half2* oh = (__half2*)&ov;
        oh[0] = __floats2half2_rn(acc[0], acc[1]);
        oh[1] = __floats2half2_rn(acc[2], acc[3]);
        oh[2] = __floats2half2_rn(acc[4], acc[5]);
        oh[3] = __floats2half2_rn(acc[6], acc[7]);
        *(uint4*)(outp + (size_t)s * HID) = ov;
        win[0] = win[1]; win[1] = win[2]; win[2] = win[3];
    }
}

// ---------------------------------------------------------------------------
// Chunked scan (2 passes), chunk length 128, 16 chunks/sequence.
// 2 h-channels per thread (a: f32, drive: f16). (Proven R12 form.)
// ---------------------------------------------------------------------------
__global__ void scan_pass1()
{
    int idx = (blockIdx.x * blockDim.x + threadIdx.x) * 2;  // over B*NCHUNK*HID
    int h = idx % HID;
    int t = idx / HID;
    int c = t % NCHUNK;
    int b = t / NCHUNK;
    size_t base = ((size_t)b * SEQ + (size_t)c * CLEN) * HID + h;
    float2 P = make_float2(1.0f, 1.0f), hs = make_float2(0.0f, 0.0f);
#pragma unroll 4
    for (int s = 0; s < CLEN; s++) {
        size_t o = base + (size_t)s * HID;
        float2 a = *(const float2*)(g_ra + o);
        __half2 dh = *(const __half2*)(g_dh + o);
        P.x *= a.x; P.y *= a.y;
        hs.x = fmaf(a.x, hs.x, __half2float(__low2half(dh)));
        hs.y = fmaf(a.y, hs.y, __half2float(__high2half(dh)));
    }
    size_t oo = ((size_t)b * NCHUNK + c) * HID + h;
    *(float2*)(g_cp + oo) = P;
    *(float2*)(g_ch + oo) = hs;
}

__global__ void scan_pass3()
{
    int idx = (blockIdx.x * blockDim.x + threadIdx.x) * 2;
    int h = idx % HID;
    int t = idx / HID;
    int c = t % NCHUNK;
    int b = t / NCHUNK;
    // stitch: fold chunk summaries 0..c-1
    float2 hin = make_float2(0.0f, 0.0f);
    for (int cc = 0; cc < c; cc++) {
        size_t oo = ((size_t)b * NCHUNK + cc) * HID + h;
        float2 p = *(const float2*)(g_cp + oo);
        float2 hh = *(const float2*)(g_ch + oo);
        hin.x = fmaf(p.x, hin.x, hh.x);
        hin.y = fmaf(p.y, hin.y, hh.y);
    }
    size_t base = ((size_t)b * SEQ + (size_t)c * CLEN) * HID + h;
    float2 hs = hin;
#pragma unroll 4
    for (int s = 0; s < CLEN; s++) {
        size_t o = base + (size_t)s * HID;
        float2 a = *(const float2*)(g_ra + o);
        __half2 dh = *(const __half2*)(g_dh + o);
        __half2 lh = *(const __half2*)(g_lefth + o);
        hs.x = fmaf(a.x, hs.x, __half2float(__low2half(dh)));
        hs.y = fmaf(a.y, hs.y, __half2float(__high2half(dh)));
        *(__half2*)(g_yh + o) =
            __floats2half2_rn(__half2float(__low2half(lh)) * hs.x,
                              __half2float(__high2half(lh)) * hs.y);
    }
}

// ---------------------------------------------------------------------------
// Launch
// ---------------------------------------------------------------------------
extern "C" void kernel_launch(void* const* d_in, const int* in_sizes, int n_in,
                              void* d_out, int out_size)
{
    const float* x      = (const float*)d_in[0];
    const float* Wl     = (const float*)d_in[1];
    const float* bl     = (const float*)d_in[2];
    const float* Wr     = (const float*)d_in[3];
    const float* br     = (const float*)d_in[4];
    const float* conv_w = (const float*)d_in[5];
    const float* conv_b = (const float*)d_in[6];
    const float* Wa     = (const float*)d_in[7];
    const float* ba     = (const float*)d_in[8];
    const float* Wi     = (const float*)d_in[9];
    const float* bi     = (const float*)d_in[10];
    const float* lam    = (const float*)d_in[11];
    const float* Wo     = (const float*)d_in[12];
    const float* bo     = (const float*)d_in[13];
    float* out = (float*)d_out;

    __half *p_wlh, *p_wrh, *p_wah, *p_wih, *p_woh;
    __half *p_lefth, *p_rinh, *p_convh, *p_rh, *p_dh, *p_yh, *p_xh;
    float *p_ra, *p_lamc;
    cudaGetSymbolAddress((void**)&p_xh,    g_xh);
    cudaGetSymbolAddress((void**)&p_wlh,   g_wlh);
    cudaGetSymbolAddress((void**)&p_wrh,   g_wrh);
    cudaGetSymbolAddress((void**)&p_wah,   g_wah);
    cudaGetSymbolAddress((void**)&p_wih,   g_wih);
    cudaGetSymbolAddress((void**)&p_woh,   g_woh);
    cudaGetSymbolAddress((void**)&p_lefth, g_lefth);
    cudaGetSymbolAddress((void**)&p_rinh,  g_rinh);
    cudaGetSymbolAddress((void**)&p_convh, g_convh);
    cudaGetSymbolAddress((void**)&p_rh,    g_rh);
    cudaGetSymbolAddress((void**)&p_dh,    g_dh);
    cudaGetSymbolAddress((void**)&p_yh,    g_yh);
    cudaGetSymbolAddress((void**)&p_ra,    g_ra);
    cudaGetSymbolAddress((void**)&p_lamc,  g_lamc);

    cudaFuncSetAttribute(gemm_h<0>, cudaFuncAttributeMaxDynamicSharedMemorySize, SM_BYTES);
    cudaFuncSetAttribute(gemm_h<2>, cudaFuncAttributeMaxDynamicSharedMemorySize, SM_BYTES);
    cudaFuncSetAttribute(gemm_h<3>, cudaFuncAttributeMaxDynamicSharedMemorySize, SM_BYTES);
    cudaFuncSetAttribute(gemm_h<4>, cudaFuncAttributeMaxDynamicSharedMemorySize, SM_BYTES);

    dim3 blk(256);
    dim3 gridHx2(2 * HID / 128, MROWS / 128);   // fused Wl+Wr
    dim3 gridH(HID / 128, MROWS / 128);
    dim3 gridO(OUTD / 128, MROWS / 128);
    int sc_blocks = (BATCH * NCHUNK * HID) / 512;   // 2 h per thread
    int cv_blocks = (BATCH * (SEQ / 8) * (HID / 8)) / 256;  // 1280

    // consolidated prep: weights transpose + lamc + x->fp16
    prep_all<<<NB_PREP, blk>>>(Wl, Wr, Wa, Wi, Wo, lam, x);

    // fused: left = gelu(x@Wl+bl) -> f16 ; rin = x@Wr+br -> f16
    gemm_h<4><<<gridHx2, blk, SM_BYTES>>>(p_xh, p_wlh, bl, nullptr, p_lefth,
                                          MROWS, HID, IND,
                                          nullptr, nullptr, nullptr, nullptr,
                                          p_wrh, br, p_rinh);

    // causal depthwise conv -> f16 (8h x 8s per thread, rolling window)
    conv_kernel<<<cv_blocks, blk>>>(conv_w, conv_b);

    // r = sigmoid(conv@Wa+ba) -> f16
    gemm_h<2><<<gridH, blk, SM_BYTES>>>(p_convh, p_wah, ba, nullptr, p_rh,
                                        MROWS, HID, HID,
                                        nullptr, nullptr, nullptr, nullptr,
                                        nullptr, nullptr, nullptr);
    // Wi-GEMM + fused gate epilogue: a -> f32, drive -> f16
    gemm_h<3><<<gridH, blk, SM_BYTES>>>(p_convh, p_wih, bi, nullptr, p_dh,
                                        MROWS, HID, HID,
                                        p_rh, p_convh, p_lamc, p_ra,
                                        nullptr, nullptr, nullptr);

    // chunked scan + y = f16(left*h)
    scan_pass1<<<sc_blocks, blk>>>();
    scan_pass3<<<sc_blocks, blk>>>();

    // out = y@Wo + bo
    gemm_h<0><<<gridO, blk, SM_BYTES>>>(p_yh, p_woh, bo, out, nullptr,
                                        MROWS, OUTD, HID,
                                        nullptr, nullptr, nullptr, nullptr,
                                        nullptr, nullptr, nullptr);
}